// round 10
// baseline (speedup 1.0000x reference)
#include <cuda_runtime.h>
#include <cuda_fp16.h>
#include <math.h>
#include <stdint.h>

// Problem constants
#define Bsz  4
#define Lseq 2048
#define Dm   1024
#define Hn   16
#define HD   64
#define Mrows (Bsz*Lseq)   // 8192
#define QLD  3072          // fused qkv row stride (halves)

// Scratch (device globals — no allocation allowed)
__device__ __half g_xh  [(size_t)Mrows * Dm];
__device__ __half g_wh  [(size_t)3 * Dm * Dm];
__device__ __half g_woh [(size_t)Dm * Dm];
__device__ __half g_qkvh[(size_t)Mrows * QLD];
__device__ __half g_th  [(size_t)Mrows * Dm];
__device__ __half g_vth [(size_t)Bsz * Hn * HD * Lseq];

// ---------------------------------------------------------------------------
__device__ __forceinline__ void cpa16(uint32_t daddr, const void* src) {
    asm volatile("cp.async.ca.shared.global [%0], [%1], 16;" :: "r"(daddr), "l"(src));
}
__device__ __forceinline__ void cpa_commit() { asm volatile("cp.async.commit_group;"); }
__device__ __forceinline__ uint32_t smem_u32(const void* p) {
    return (uint32_t)__cvta_generic_to_shared(p);
}
__device__ __forceinline__ void ldsm4(uint32_t* r, uint32_t a) {
    asm volatile("ldmatrix.sync.aligned.m8n8.x4.shared.b16 {%0,%1,%2,%3}, [%4];"
                 : "=r"(r[0]), "=r"(r[1]), "=r"(r[2]), "=r"(r[3]) : "r"(a));
}
__device__ __forceinline__ void mmaf16(float* d, const uint32_t* a, uint32_t b0, uint32_t b1) {
    asm volatile(
        "mma.sync.aligned.m16n8k16.row.col.f32.f16.f16.f32 "
        "{%0,%1,%2,%3}, {%4,%5,%6,%7}, {%8,%9}, {%0,%1,%2,%3};"
        : "+f"(d[0]), "+f"(d[1]), "+f"(d[2]), "+f"(d[3])
        : "r"(a[0]), "r"(a[1]), "r"(a[2]), "r"(a[3]), "r"(b0), "r"(b1));
}
// pack two fp32 -> one fp16x2 register
__device__ __forceinline__ uint32_t packh2(float lo, float hi) {
    uint32_t u;
    asm("cvt.rn.f16x2.f32 %0, %1, %2;" : "=r"(u) : "f"(hi), "f"(lo));
    return u;
}

// ---------------------------------------------------------------------------
// fp16 NT GEMM: C = alpha * A[M,K] @ B[N,K]^T (+bias)
// MODE 0: proj -> fp16 C.  MODE 3: out proj -> fp32 C + bias.
// ---------------------------------------------------------------------------
template<int BN, int MODE>
__global__ __launch_bounds__(256) void hgemm(
    const __half* __restrict__ Ag, const __half* __restrict__ Bg,
    const float* __restrict__ bias, void* __restrict__ Cg,
    int K, int lda, int ldb, int ldc, float alpha)
{
    constexpr int WN = BN / 4;
    constexpr int NG = WN / 16;
    constexpr int NJ = WN / 8;
    constexpr int ABYTES = 128 * 64;
    constexpr int BBYTES = BN * 64;
    constexpr int STAGE = ABYTES + BBYTES;

    extern __shared__ char smem[];
    const uint32_t sb = smem_u32(smem);

    const int tid = threadIdx.x;
    const int w = tid >> 5, lane = tid & 31;
    const int wm = (w >> 2) * 64, wn = (w & 3) * WN;
    const int g = lane >> 2, tig = lane & 3;
    const int l15 = lane & 15, lh = lane >> 4;
    const int sel = (l15 >> 1) & 3;

    const int m0 = blockIdx.y * 128;
    const int n0 = blockIdx.x * BN;

    const __half* Ab = Ag + (size_t)m0 * lda;
    const __half* Bb = Bg + (size_t)n0 * ldb;
    float* Cf = nullptr;
    __half* Ch = nullptr;
    if (MODE == 0) Ch = (__half*)Cg + (size_t)m0 * ldc + n0;
    else           Cf = (float*)Cg + (size_t)m0 * ldc + n0;

    float acc[4][NJ][4];
    #pragma unroll
    for (int i = 0; i < 4; i++)
        #pragma unroll
        for (int j = 0; j < NJ; j++)
            #pragma unroll
            for (int r = 0; r < 4; r++) acc[i][j][r] = 0.f;

    const int nk = K / 32;

    auto ldA = [&](int kt, int st) {
        const uint32_t base = sb + st * STAGE;
        const int r = tid >> 1;
        const int c0 = (tid & 1) * 2;
        const __half* src = Ab + (size_t)r * lda + kt * 32;
        #pragma unroll
        for (int c = 0; c < 2; c++) {
            const int cc = c0 + c;
            cpa16(base + r * 64 + ((cc ^ ((r >> 1) & 3)) * 16), src + cc * 8);
        }
    };
    auto ldB = [&](int kt, int st) {
        const uint32_t base = sb + st * STAGE + ABYTES;
        const int r = tid >> 1;
        const int c0 = (tid & 1) * 2;
        const __half* src = Bb + (size_t)r * ldb + kt * 32;
        #pragma unroll
        for (int c = 0; c < 2; c++) {
            const int cc = c0 + c;
            cpa16(base + r * 64 + ((cc ^ ((r >> 1) & 3)) * 16), src + cc * 8);
        }
    };

    int issued = 0;
    #pragma unroll
    for (int t = 0; t < 3; t++)
        if (t < nk) { ldA(t, t); ldB(t, t); cpa_commit(); issued++; }

    for (int kt = 0; kt < nk; kt++) {
        const int pend = issued - (kt + 1);
        if (pend <= 0)      asm volatile("cp.async.wait_group 0;");
        else if (pend == 1) asm volatile("cp.async.wait_group 1;");
        else                asm volatile("cp.async.wait_group 2;");
        __syncthreads();

        const int st = kt % 3;
        const uint32_t aB = sb + st * STAGE;
        const uint32_t bB = aB + ABYTES;

        #pragma unroll
        for (int ks = 0; ks < 2; ks++) {
            const uint32_t chunk = ((uint32_t)(lh + 2 * ks) ^ (uint32_t)sel) * 16;
            uint32_t af[4][4];
            #pragma unroll
            for (int i = 0; i < 4; i++)
                ldsm4(af[i], aB + (wm + 16 * i + l15) * 64 + chunk);
            uint32_t bf[NG][4];
            #pragma unroll
            for (int jg = 0; jg < NG; jg++)
                ldsm4(bf[jg], bB + (wn + 16 * jg + l15) * 64 + chunk);
            #pragma unroll
            for (int i = 0; i < 4; i++)
                #pragma unroll
                for (int jg = 0; jg < NG; jg++) {
                    mmaf16(acc[i][2 * jg + 0], af[i], bf[jg][0], bf[jg][2]);
                    mmaf16(acc[i][2 * jg + 1], af[i], bf[jg][1], bf[jg][3]);
                }
        }
        __syncthreads();

        if (issued < nk) {
            ldA(issued, issued % 3); ldB(issued, issued % 3);
            cpa_commit();
            issued++;
        }
    }

    #pragma unroll
    for (int i = 0; i < 4; i++) {
        const int row = wm + 16 * i + g;
        #pragma unroll
        for (int j = 0; j < NJ; j++) {
            const int col = wn + 8 * j + 2 * tig;
            float a0 = acc[i][j][0], a1 = acc[i][j][1];
            float a2 = acc[i][j][2], a3 = acc[i][j][3];
            if (MODE == 3) {
                const float b0 = bias[n0 + col], b1 = bias[n0 + col + 1];
                a0 += b0; a1 += b1; a2 += b0; a3 += b1;
            }
            if (MODE == 0) {
                *(uint32_t*)(Ch + (size_t)row * ldc + col)       = packh2(a0, a1);
                *(uint32_t*)(Ch + (size_t)(row + 8) * ldc + col) = packh2(a2, a3);
            } else {
                *(float2*)(Cf + (size_t)row * ldc + col)       = make_float2(a0, a1);
                *(float2*)(Cf + (size_t)(row + 8) * ldc + col) = make_float2(a2, a3);
            }
        }
    }
}

// ---------------------------------------------------------------------------
// Fully fused attention: scores + softmax + A write + A@V.
// One CTA = 16 query rows of one (b,h). 256 threads (8 warps).
// AV split: warp w -> d-group (w&3)*16, k-chunks (w>>2)*4..+4; smem reduction.
// smem: Q 2KB | K/V dblbuf 2x32KB | A fp16 tile 8KB | stats 128B | scores 128.5KB
// ---------------------------------------------------------------------------
#define ASM_Q 0
#define ASM_K 2048
#define ASM_AT (2048 + 65536)          // 67584 (A tile 8KB; reused as reduction buf)
#define ASM_STAT (ASM_AT + 8192)       // 75776
#define ASM_S (ASM_STAT + 128)         // 75904
#define SSTRIDE 2056
#define ASM_TOTAL (ASM_S + 16 * SSTRIDE * 4)   // 207488
#define RED_STRIDE 18                  // 16x16 partial tile, padded stride

__global__ __launch_bounds__(256) void attn_fused(
    const __half* __restrict__ qkvh, const __half* __restrict__ vth,
    float* __restrict__ Aout, __half* __restrict__ thOut)
{
    extern __shared__ char smem[];
    const uint32_t sb = smem_u32(smem);
    float* scoresS = (float*)(smem + ASM_S);
    float* statS   = (float*)(smem + ASM_STAT);

    const int tid = threadIdx.x;
    const int w = tid >> 5, lane = tid & 31;
    const int l15 = lane & 15, lh = lane >> 4, sel = (l15 >> 1) & 3;
    const int g = lane >> 2, tig = lane & 3;

    const int l0 = blockIdx.x * 16;
    const int z  = blockIdx.y;
    const int b = z >> 4, h = z & 15;

    const __half* qb = qkvh + ((size_t)b * Lseq + l0) * QLD + h * HD;
    const __half* kb = qkvh + (size_t)b * Lseq * QLD + Dm + h * HD;
    const __half* vb = vth + (size_t)z * HD * Lseq;

    // Q load
    if (tid < 128) {
        const int row = tid >> 3, col8 = tid & 7;
        const int p = col8 >> 2, c = col8 & 3;
        cpa16(sb + ASM_Q + p * 1024 + row * 64 + ((c ^ ((row >> 1) & 3)) * 16),
              qb + (size_t)row * QLD + col8 * 8);
    }
    auto ldK = [&](int nt, int buf) {
        const int col8 = tid & 7;
        const int p = col8 >> 2, c = col8 & 3;
        #pragma unroll
        for (int i = 0; i < 8; i++) {
            const int row = (tid >> 3) + i * 32;
            cpa16(sb + ASM_K + buf * 32768 + p * 16384 + row * 64 +
                      ((c ^ ((row >> 1) & 3)) * 16),
                  kb + (size_t)(nt * 256 + row) * QLD + col8 * 8);
        }
    };
    // V panel: 64 d-rows x 256 s-cols, 8 chunks (k=32) of 64 rows x 64B
    auto ldV = [&](int nt, int buf) {
        const int r = tid >> 2;            // 0..63
        const int u0 = (tid & 3) * 8;
        const __half* src = vb + (size_t)r * Lseq + nt * 256;
        #pragma unroll
        for (int i = 0; i < 8; i++) {
            const int u = u0 + i;          // 0..31
            const int kk = u >> 2, c8 = u & 3;
            cpa16(sb + ASM_K + buf * 32768 + kk * 4096 + r * 64 +
                      ((c8 ^ ((r >> 1) & 3)) * 16),
                  src + u * 8);
        }
    };

    ldK(0, 0); cpa_commit();
    ldK(1, 1); cpa_commit();

    asm volatile("cp.async.wait_group 1;");
    __syncthreads();

    // Q fragments (held through scores phase)
    uint32_t qf[4][4];
    #pragma unroll
    for (int kk = 0; kk < 4; kk++) {
        const int kh = kk >> 1, ks = kk & 1;
        ldsm4(qf[kk], sb + ASM_Q + kh * 1024 + l15 * 64 + (((lh + 2 * ks) ^ sel) * 16));
    }

    // ---- scores phase ----
    for (int nt = 0; nt < 8; nt++) {
        if (nt > 0) {
            if (nt < 7) asm volatile("cp.async.wait_group 1;");
            else        asm volatile("cp.async.wait_group 0;");
            __syncthreads();
        }
        const uint32_t Kb = sb + ASM_K + (nt & 1) * 32768;

        float acc[4][4];
        #pragma unroll
        for (int j = 0; j < 4; j++)
            #pragma unroll
            for (int r = 0; r < 4; r++) acc[j][r] = 0.f;

        #pragma unroll
        for (int kk = 0; kk < 4; kk++) {
            const int kh = kk >> 1, ks = kk & 1;
            const uint32_t chunk = (((uint32_t)lh + 2 * ks) ^ (uint32_t)sel) * 16;
            uint32_t bf0[4], bf1[4];
            ldsm4(bf0, Kb + kh * 16384 + (w * 32 + l15) * 64 + chunk);
            ldsm4(bf1, Kb + kh * 16384 + (w * 32 + 16 + l15) * 64 + chunk);
            mmaf16(acc[0], qf[kk], bf0[0], bf0[2]);
            mmaf16(acc[1], qf[kk], bf0[1], bf0[3]);
            mmaf16(acc[2], qf[kk], bf1[0], bf1[2]);
            mmaf16(acc[3], qf[kk], bf1[1], bf1[3]);
        }

        #pragma unroll
        for (int j = 0; j < 4; j++) {
            const int col = nt * 256 + w * 32 + j * 8 + 2 * tig;
            *(float2*)&scoresS[g * SSTRIDE + col] =
                make_float2(acc[j][0] * 0.125f, acc[j][1] * 0.125f);
            *(float2*)&scoresS[(g + 8) * SSTRIDE + col] =
                make_float2(acc[j][2] * 0.125f, acc[j][3] * 0.125f);
        }
        __syncthreads();
        if (nt + 2 < 8) { ldK(nt + 2, nt & 1); cpa_commit(); }
    }
    // all K loads drained; K buffers free for V

    // V prologue (overlap with stats pass)
    ldV(0, 0); cpa_commit();
    ldV(1, 1); cpa_commit();
    int vIssued = 2;

    // ---- pass 1: per-row softmax stats ----
    #pragma unroll
    for (int rr = 0; rr < 2; rr++) {
        const int r = w + rr * 8;
        const float* rp = &scoresS[r * SSTRIDE];
        float vals[64];
        float m = -INFINITY;
        #pragma unroll
        for (int c = 0; c < 16; c++) {
            float4 vv = *(const float4*)&rp[lane * 4 + c * 128];
            vals[4 * c + 0] = vv.x; vals[4 * c + 1] = vv.y;
            vals[4 * c + 2] = vv.z; vals[4 * c + 3] = vv.w;
            m = fmaxf(m, fmaxf(fmaxf(vv.x, vv.y), fmaxf(vv.z, vv.w)));
        }
        #pragma unroll
        for (int o = 16; o; o >>= 1) m = fmaxf(m, __shfl_xor_sync(0xffffffffu, m, o));
        float s = 0.f;
        #pragma unroll
        for (int i = 0; i < 64; i++) s += __expf(vals[i] - m);
        #pragma unroll
        for (int o = 16; o; o >>= 1) s += __shfl_xor_sync(0xffffffffu, s, o);
        if (lane == 0) { statS[r] = m; statS[16 + r] = 1.0f / s; }
    }
    __syncthreads();

    // ---- pass 2: per-panel convert + write A + AV MMA ----
    // warp w: d-group (w&3)*16, k-chunks (w>>2)*4 .. +4
    float oacc[2][4];
    #pragma unroll
    for (int j = 0; j < 2; j++)
        #pragma unroll
        for (int r = 0; r < 4; r++) oacc[j][r] = 0.f;

    const int dgrp = (w & 3) * 16;
    const int kh0  = (w >> 2) * 4;

    const int crow = tid >> 4;        // 0..15
    const int cg = tid & 15;          // 0..15
    const float rm   = statS[crow];
    const float rinv = statS[16 + crow];

    for (int nt = 0; nt < 8; nt++) {
        const int pend = vIssued - (nt + 1);
        if (pend <= 0) asm volatile("cp.async.wait_group 0;");
        else           asm volatile("cp.async.wait_group 1;");
        __syncthreads();   // V panel ready; previous panel's MMA done everywhere

        if (nt >= 1 && nt + 1 < 8) {
            ldV(nt + 1, (nt + 1) & 1);
            cpa_commit();
            vIssued++;
        }

        // convert scores panel -> fp32 A gmem + fp16 A smem tile
        {
            const float* rp = &scoresS[crow * SSTRIDE + nt * 256 + cg * 16];
            float* op = Aout + ((size_t)z * Lseq + l0 + crow) * Lseq + nt * 256 + cg * 16;
            uint32_t hbuf[8];
            #pragma unroll
            for (int q = 0; q < 4; q++) {
                float4 v = *(const float4*)(rp + 4 * q);
                v.x = __expf(v.x - rm) * rinv;
                v.y = __expf(v.y - rm) * rinv;
                v.z = __expf(v.z - rm) * rinv;
                v.w = __expf(v.w - rm) * rinv;
                *(float4*)(op + 4 * q) = v;
                hbuf[2 * q + 0] = packh2(v.x, v.y);
                hbuf[2 * q + 1] = packh2(v.z, v.w);
            }
            #pragma unroll
            for (int un = 0; un < 2; un++) {
                const int u = cg * 2 + un;
                const int kk = u >> 2, c8 = u & 3;
                *(uint4*)(smem + ASM_AT + kk * 1024 + crow * 64 +
                          ((c8 ^ ((crow >> 1) & 3)) * 16)) =
                    make_uint4(hbuf[4 * un + 0], hbuf[4 * un + 1],
                               hbuf[4 * un + 2], hbuf[4 * un + 3]);
            }
        }
        __syncthreads();   // A tile visible

        // AV MMA: A(16 x k-half) @ Vpanel chunk -> accumulate 16x16 partial
        const uint32_t Vb = sb + ASM_K + (nt & 1) * 32768;
        #pragma unroll
        for (int kc = 0; kc < 4; kc++) {
            const int kk = kh0 + kc;
            #pragma unroll
            for (int ks = 0; ks < 2; ks++) {
                const uint32_t chunk = (((uint32_t)lh + 2 * ks) ^ (uint32_t)sel) * 16;
                uint32_t af[4], bf[4];
                ldsm4(af, sb + ASM_AT + kk * 1024 + l15 * 64 + chunk);
                ldsm4(bf, Vb + kk * 4096 + (dgrp + l15) * 64 + chunk);
                mmaf16(oacc[0], af, bf[0], bf[2]);
                mmaf16(oacc[1], af, bf[1], bf[3]);
            }
        }
    }

    // ---- reduction of the two k-halves + epilogue ----
    __syncthreads();   // all MMAs done; A-tile buffer reusable as reduction buf
    float* redbuf = (float*)(smem + ASM_AT);
    if (w >= 4) {
        float* rb = redbuf + (w - 4) * (16 * RED_STRIDE);
        #pragma unroll
        for (int j = 0; j < 2; j++) {
            const int col = j * 8 + 2 * tig;
            *(float2*)&rb[g * RED_STRIDE + col]       = make_float2(oacc[j][0], oacc[j][1]);
            *(float2*)&rb[(g + 8) * RED_STRIDE + col] = make_float2(oacc[j][2], oacc[j][3]);
        }
    }
    __syncthreads();
    if (w < 4) {
        float* rb = redbuf + w * (16 * RED_STRIDE);
        __half* op = thOut + ((size_t)b * Lseq + l0) * Dm + (size_t)h * HD + dgrp;
        #pragma unroll
        for (int j = 0; j < 2; j++) {
            const int col = j * 8 + 2 * tig;
            float2 p0 = *(float2*)&rb[g * RED_STRIDE + col];
            float2 p1 = *(float2*)&rb[(g + 8) * RED_STRIDE + col];
            *(uint32_t*)(op + (size_t)g * Dm + col) =
                packh2(oacc[j][0] + p0.x, oacc[j][1] + p0.y);
            *(uint32_t*)(op + (size_t)(g + 8) * Dm + col) =
                packh2(oacc[j][2] + p1.x, oacc[j][3] + p1.y);
        }
    }
}

// ---------------------------------------------------------------------------
__global__ void cvt_h(const float* __restrict__ s, __half* __restrict__ d, int n8)
{
    int i = blockIdx.x * blockDim.x + threadIdx.x;
    if (i < n8) {
        float4 v0 = ((const float4*)s)[2 * i];
        float4 v1 = ((const float4*)s)[2 * i + 1];
        uint4 o;
        o.x = packh2(v0.x, v0.y);
        o.y = packh2(v0.z, v0.w);
        o.z = packh2(v1.x, v1.y);
        o.w = packh2(v1.z, v1.w);
        ((uint4*)d)[i] = o;
    }
}

// ---------------------------------------------------------------------------
__global__ __launch_bounds__(256) void transpose_v(
    const __half* __restrict__ qkvh, __half* __restrict__ vt)
{
    __shared__ __half tile[32][33];
    const int z = blockIdx.z, b = z >> 4, h = z & 15;
    const int s0 = blockIdx.x * 32;
    const int d0 = blockIdx.y * 32;
    const int tx = threadIdx.x, ty = threadIdx.y;

    const __half* src = qkvh + (size_t)b * Lseq * QLD + 2 * Dm + (size_t)h * HD;
    #pragma unroll
    for (int i = 0; i < 32; i += 8)
        tile[ty + i][tx] = src[(size_t)(s0 + ty + i) * QLD + d0 + tx];
    __syncthreads();
    __half* dst = vt + (size_t)z * HD * Lseq;
    #pragma unroll
    for (int i = 0; i < 32; i += 8)
        dst[(size_t)(d0 + ty + i) * Lseq + s0 + tx] = tile[tx][ty + i];
}

// ---------------------------------------------------------------------------
extern "C" void kernel_launch(void* const* d_in, const int* in_sizes, int n_in,
                              void* d_out, int out_size)
{
    const float* x  = (const float*)d_in[0];
    // d_in[1] = key_indices (unused by the reference)
    const float* Wq = (const float*)d_in[2];
    const float* Wk = (const float*)d_in[3];
    const float* Wv = (const float*)d_in[4];
    const float* Wo = (const float*)d_in[5];
    const float* bo = (const float*)d_in[6];

    float* outp = (float*)d_out;
    float* Aout = outp + (size_t)Mrows * Dm;

    __half *xh, *wh, *woh, *qkvh, *th, *vth;
    cudaGetSymbolAddress((void**)&xh,   g_xh);
    cudaGetSymbolAddress((void**)&wh,   g_wh);
    cudaGetSymbolAddress((void**)&woh,  g_woh);
    cudaGetSymbolAddress((void**)&qkvh, g_qkvh);
    cudaGetSymbolAddress((void**)&th,   g_th);
    cudaGetSymbolAddress((void**)&vth,  g_vth);

    const int SM128 = 3 * (8192 + 8192);
    cudaFuncSetAttribute(hgemm<128, 0>, cudaFuncAttributeMaxDynamicSharedMemorySize, SM128);
    cudaFuncSetAttribute(hgemm<128, 3>, cudaFuncAttributeMaxDynamicSharedMemorySize, SM128);
    cudaFuncSetAttribute(attn_fused,    cudaFuncAttributeMaxDynamicSharedMemorySize, ASM_TOTAL);

    // fp16 conversions
    const int nx8 = Mrows * Dm / 8;
    const int nw8 = Dm * Dm / 8;
    cvt_h<<<(nx8 + 255) / 256, 256>>>(x,  xh,               nx8);
    cvt_h<<<(nw8 + 255) / 256, 256>>>(Wq, wh,               nw8);
    cvt_h<<<(nw8 + 255) / 256, 256>>>(Wk, wh + Dm * Dm,     nw8);
    cvt_h<<<(nw8 + 255) / 256, 256>>>(Wv, wh + 2 * Dm * Dm, nw8);
    cvt_h<<<(nw8 + 255) / 256, 256>>>(Wo, woh,              nw8);

    // fused QKV projection
    {
        dim3 g(QLD / 128, Mrows / 128, 1);
        hgemm<128, 0><<<g, 256, SM128>>>(xh, wh, nullptr, qkvh,
                                         Dm, Dm, Dm, QLD, 1.0f);
    }
    // transpose v -> vT[z][d][s]  (needed by fused attention)
    {
        dim3 g(Lseq / 32, HD / 32, Bsz * Hn);
        transpose_v<<<g, dim3(32, 8)>>>(qkvh, vth);
    }
    // fully fused attention: scores + softmax + A + A@V
    {
        dim3 g(Lseq / 16, Bsz * Hn);   // (128, 64)
        attn_fused<<<g, 256, ASM_TOTAL>>>(qkvh, vth, Aout, th);
    }
    // output projection with bias
    {
        dim3 g(Dm / 128, Mrows / 128, 1);
        hgemm<128, 3><<<g, 256, SM128>>>(th, woh, bo, outp,
                                         Dm, Dm, Dm, Dm, 1.0f);
    }
}